// round 7
// baseline (speedup 1.0000x reference)
#include <cuda_runtime.h>
#include <cuda_bf16.h>

// Problem constants
#define BATCH   2
#define SEQ     2048
#define DMODEL  1024
#define NHEAD   16
#define DK      64
#define MROWS   (BATCH * SEQ)       // 4096

// ---------------------------------------------------------------------------
// Scratch (no allocations allowed -> device globals)
// ---------------------------------------------------------------------------
__device__ float g_Q[MROWS * DMODEL];
__device__ float g_K[MROWS * DMODEL];
__device__ float g_V[MROWS * DMODEL];
__device__ float g_X[MROWS * DMODEL];   // attention output (pre out-proj)

// ---------------------------------------------------------------------------
// Packed fp32x2 helpers (Blackwell double-rate fp32 path)
// ---------------------------------------------------------------------------
__device__ __forceinline__ unsigned long long pack2(float lo, float hi) {
    unsigned long long r;
    asm("mov.b64 %0, {%1, %2};" : "=l"(r) : "f"(lo), "f"(hi));
    return r;
}
__device__ __forceinline__ float2 unpack2(unsigned long long x) {
    float2 r;
    asm("mov.b64 {%0, %1}, %2;" : "=f"(r.x), "=f"(r.y) : "l"(x));
    return r;
}
__device__ __forceinline__ unsigned long long ffma2(unsigned long long a,
                                                    unsigned long long b,
                                                    unsigned long long c) {
    unsigned long long d;
    asm("fma.rn.f32x2 %0, %1, %2, %3;" : "=l"(d) : "l"(a), "l"(b), "l"(c));
    return d;
}
__device__ __forceinline__ unsigned long long fmul2(unsigned long long a,
                                                    unsigned long long b) {
    unsigned long long d;
    asm("mul.rn.f32x2 %0, %1, %2;" : "=l"(d) : "l"(a), "l"(b));
    return d;
}

// cp.async helpers (16B, bypass-L1 .cg path)
__device__ __forceinline__ void cp_async16(void* smem_ptr, const void* gptr) {
    unsigned saddr = (unsigned)__cvta_generic_to_shared(smem_ptr);
    asm volatile("cp.async.cg.shared.global [%0], [%1], 16;"
                 :: "r"(saddr), "l"(gptr) : "memory");
}
__device__ __forceinline__ void cp_commit() {
    asm volatile("cp.async.commit_group;" ::: "memory");
}
__device__ __forceinline__ void cp_wait0() {
    asm volatile("cp.async.wait_group 0;" ::: "memory");
}

// ---------------------------------------------------------------------------
// NT GEMM: C[m,n] = sum_k A[m,k] * W[n,k];  tiles 128x128x16, 256 threads.
// Double-buffered smem, ONE __syncthreads per k-tile, register prefetch.
// Thread (ty,tx): rows m0+8ty..+7, cols n0+8tx..+7 (4 f32x2 pairs).
// A duplicated in smem so the f32x2 'a' operand loads need no packing.
// ---------------------------------------------------------------------------
__device__ __forceinline__ void gemm_nt_body(const float* __restrict__ A,
                                             const float* __restrict__ W,
                                             float* __restrict__ C) {
    __shared__ __align__(16) float As2[2][16][256];   // [buf][k][2*m] duplicated
    __shared__ __align__(16) float Bs[2][16][128];    // [buf][k][n]

    const int tid = threadIdx.x;
    const int m0 = blockIdx.y * 128;
    const int n0 = blockIdx.x * 128;
    const int ty = tid >> 4;      // 0..15
    const int tx = tid & 15;      // 0..15

    const int r0 = tid >> 2;      // 0..63
    const int r1 = r0 + 64;
    const int c4 = tid & 3;       // float4 column within 16-wide k slab

    const float4* A4 = (const float4*)A;
    const float4* W4 = (const float4*)W;

    unsigned long long acc[8][4];
#pragma unroll
    for (int i = 0; i < 8; i++)
#pragma unroll
        for (int p = 0; p < 4; p++) acc[i][p] = 0ull;

    float4 pa0, pa1, pb0, pb1;

#define GEMM_LDG(kt)                                               \
    do {                                                           \
        const int ko = (kt) * 4;                                   \
        pa0 = A4[(size_t)(m0 + r0) * 256 + ko + c4];               \
        pa1 = A4[(size_t)(m0 + r1) * 256 + ko + c4];               \
        pb0 = W4[(size_t)(n0 + r0) * 256 + ko + c4];               \
        pb1 = W4[(size_t)(n0 + r1) * 256 + ko + c4];               \
    } while (0)

#define GEMM_STS(buf)                                              \
    do {                                                           \
        const int kc = c4 * 4;                                     \
        *(float2*)&As2[buf][kc + 0][2 * r0] = make_float2(pa0.x, pa0.x); \
        *(float2*)&As2[buf][kc + 1][2 * r0] = make_float2(pa0.y, pa0.y); \
        *(float2*)&As2[buf][kc + 2][2 * r0] = make_float2(pa0.z, pa0.z); \
        *(float2*)&As2[buf][kc + 3][2 * r0] = make_float2(pa0.w, pa0.w); \
        *(float2*)&As2[buf][kc + 0][2 * r1] = make_float2(pa1.x, pa1.x); \
        *(float2*)&As2[buf][kc + 1][2 * r1] = make_float2(pa1.y, pa1.y); \
        *(float2*)&As2[buf][kc + 2][2 * r1] = make_float2(pa1.z, pa1.z); \
        *(float2*)&As2[buf][kc + 3][2 * r1] = make_float2(pa1.w, pa1.w); \
        Bs[buf][kc + 0][r0] = pb0.x;                               \
        Bs[buf][kc + 1][r0] = pb0.y;                               \
        Bs[buf][kc + 2][r0] = pb0.z;                               \
        Bs[buf][kc + 3][r0] = pb0.w;                               \
        Bs[buf][kc + 0][r1] = pb1.x;                               \
        Bs[buf][kc + 1][r1] = pb1.y;                               \
        Bs[buf][kc + 2][r1] = pb1.z;                               \
        Bs[buf][kc + 3][r1] = pb1.w;                               \
    } while (0)

    // prologue: tile 0 staged, tile 1 prefetched
    GEMM_LDG(0);
    GEMM_STS(0);
    GEMM_LDG(1);

    for (int kt = 0; kt < 64; kt++) {
        const int cur = kt & 1;
        __syncthreads();   // publishes buf[cur]; guarantees buf[cur^1] is free

        if (kt < 63) GEMM_STS(cur ^ 1);   // stage tile kt+1
        if (kt < 62) GEMM_LDG(kt + 2);    // prefetch tile kt+2

        // ---- compute 16 k-steps from buf[cur] ----
#pragma unroll
        for (int kk = 0; kk < 16; kk++) {
            unsigned long long a2[8];
            const ulonglong2* Ar = (const ulonglong2*)&As2[cur][kk][ty * 16];
#pragma unroll
            for (int i = 0; i < 4; i++) {
                ulonglong2 t = Ar[i];
                a2[2 * i]     = t.x;
                a2[2 * i + 1] = t.y;
            }
            const ulonglong2* Br = (const ulonglong2*)&Bs[cur][kk][8 * tx];
            ulonglong2 tb0 = Br[0];
            ulonglong2 tb1 = Br[1];
            unsigned long long b2[4] = {tb0.x, tb0.y, tb1.x, tb1.y};
#pragma unroll
            for (int i = 0; i < 8; i++)
#pragma unroll
                for (int p = 0; p < 4; p++)
                    acc[i][p] = ffma2(a2[i], b2[p], acc[i][p]);
        }
    }
#undef GEMM_LDG
#undef GEMM_STS

    // ---- epilogue: 8 contiguous floats per row -> two 16B stores ----
    float* Cr = C + (size_t)(m0 + ty * 8) * 1024 + n0 + 8 * tx;
#pragma unroll
    for (int i = 0; i < 8; i++) {
        *(ulonglong2*)(Cr + (size_t)i * 1024)     = make_ulonglong2(acc[i][0], acc[i][1]);
        *(ulonglong2*)(Cr + (size_t)i * 1024 + 4) = make_ulonglong2(acc[i][2], acc[i][3]);
    }
}

__global__ void __launch_bounds__(256, 2)
mha_gemm_qkv(const float* __restrict__ q, const float* __restrict__ k,
             const float* __restrict__ v, const float* __restrict__ wq,
             const float* __restrict__ wk, const float* __restrict__ wv) {
    const int z = blockIdx.z;
    const float* A = (z == 0) ? q : (z == 1) ? k : v;
    const float* W = (z == 0) ? wq : (z == 1) ? wk : wv;
    float* C = (z == 0) ? g_Q : (z == 1) ? g_K : g_V;
    gemm_nt_body(A, W, C);
}

__global__ void __launch_bounds__(256, 2)
mha_gemm_out(const float* __restrict__ wo, float* __restrict__ out) {
    gemm_nt_body(g_X, wo, out);
}

// ---------------------------------------------------------------------------
// Flash attention: CTA = 128 query rows x one (batch, head); 128 threads,
// thread t owns row q0+t. K/V tiles (32x64) double-buffered via cp.async,
// one __syncthreads per tile. Scores staged in smem (stride 33, no conflicts).
// ---------------------------------------------------------------------------
#define ATT_BM 128
#define ATT_BN 32
#define ATT_SS_STRIDE 33
#define ATT_TILE_F (ATT_BN * DK)                    // 2048 floats per K or V buffer
#define ATT_SMEM_FLOATS (4 * ATT_TILE_F + ATT_BM * ATT_SS_STRIDE)
#define ATT_SMEM_BYTES (ATT_SMEM_FLOATS * 4)        // 49664 bytes

__device__ __forceinline__ void att_issue_tile(float* KsB, float* VsB,
                                               int b, int h, int j0, int t) {
    const float* Kg = g_K + ((size_t)(b * SEQ + j0)) * DMODEL + h * DK;
    const float* Vg = g_V + ((size_t)(b * SEQ + j0)) * DMODEL + h * DK;
#pragma unroll
    for (int it = 0; it < 4; it++) {
        const int idx = t + it * 128;       // 0..511 over 32 rows x 16 float4
        const int r = idx >> 4;
        const int c = idx & 15;
        cp_async16(KsB + r * DK + c * 4, Kg + (size_t)r * DMODEL + c * 4);
        cp_async16(VsB + r * DK + c * 4, Vg + (size_t)r * DMODEL + c * 4);
    }
    cp_commit();
}

__global__ void __launch_bounds__(128, 3)
mha_flash_attn(const int* __restrict__ mask) {
    extern __shared__ __align__(16) float smf[];
    float* Ks[2] = {smf, smf + ATT_TILE_F};
    float* Vs[2] = {smf + 2 * ATT_TILE_F, smf + 3 * ATT_TILE_F};
    float* Ss    = smf + 4 * ATT_TILE_F;

    const int t  = threadIdx.x;
    const int q0 = blockIdx.x * ATT_BM;
    const int bh = blockIdx.y;
    const int b  = bh >> 4;
    const int h  = bh & 15;
    const int row = b * SEQ + q0 + t;

    // q row (64 floats) as 32 packed pairs
    unsigned long long q2[32];
    {
        const ulonglong2* Qr =
            (const ulonglong2*)(g_Q + (size_t)row * DMODEL + h * DK);
#pragma unroll
        for (int i = 0; i < 16; i++) {
            ulonglong2 tq = Qr[i];
            q2[2 * i]     = tq.x;
            q2[2 * i + 1] = tq.y;
        }
    }
    unsigned long long o2[32];
#pragma unroll
    for (int i = 0; i < 32; i++) o2[i] = 0ull;

    float m_i = -1e30f;
    float l_i = 0.0f;

    const int* mrow = mask + ((size_t)b * SEQ + (q0 + t)) * SEQ;
    float* ssrow = Ss + t * ATT_SS_STRIDE;

    // prologue: tile 0 in flight
    att_issue_tile(Ks[0], Vs[0], b, h, 0, t);

    const int NT = SEQ / ATT_BN;   // 64 tiles
    for (int n = 0; n < NT; n++) {
        const int cur = n & 1;
        const int j0 = n * ATT_BN;

        cp_wait0();
        __syncthreads();           // tile n visible; prev compute done

        if (n + 1 < NT)
            att_issue_tile(Ks[cur ^ 1], Vs[cur ^ 1], b, h, j0 + ATT_BN, t);

        const float* Kc = Ks[cur];
        const float* Vc = Vs[cur];

        // ---- scores: s_j = (q . K_j) / 8, masked; 4 independent fma chains ----
        float tmax = -1e30f;
#pragma unroll
        for (int j4 = 0; j4 < ATT_BN / 4; j4++) {
            const int4 mv = *(const int4*)(mrow + j0 + j4 * 4);
            const int mvals[4] = {mv.x, mv.y, mv.z, mv.w};
#pragma unroll
            for (int jj = 0; jj < 4; jj++) {
                const int j = j4 * 4 + jj;
                const ulonglong2* k2 = (const ulonglong2*)(Kc + j * DK);
                unsigned long long ax0 = 0ull, ax1 = 0ull, ay0 = 0ull, ay1 = 0ull;
#pragma unroll
                for (int c = 0; c < 16; c += 2) {
                    ulonglong2 kv0 = k2[c];
                    ulonglong2 kv1 = k2[c + 1];
                    ax0 = ffma2(q2[2 * c],     kv0.x, ax0);
                    ay0 = ffma2(q2[2 * c + 1], kv0.y, ay0);
                    ax1 = ffma2(q2[2 * c + 2], kv1.x, ax1);
                    ay1 = ffma2(q2[2 * c + 3], kv1.y, ay1);
                }
                float2 x0 = unpack2(ax0);
                float2 x1 = unpack2(ax1);
                float2 y0 = unpack2(ay0);
                float2 y1 = unpack2(ay1);
                float s = ((x0.x + x0.y) + (x1.x + x1.y)) +
                          ((y0.x + y0.y) + (y1.x + y1.y));
                s *= 0.125f;
                if (mvals[jj] == 0) s = -1e9f;
                ssrow[j] = s;
                tmax = fmaxf(tmax, s);
            }
        }

        // ---- online softmax rescale ----
        const float m_new = fmaxf(m_i, tmax);
        const float alpha = __expf(m_i - m_new);
        l_i *= alpha;
        {
            const unsigned long long a2 = pack2(alpha, alpha);
#pragma unroll
            for (int c = 0; c < 32; c++) o2[c] = fmul2(o2[c], a2);
        }

        // ---- accumulate P @ V ----
        for (int j = 0; j < ATT_BN; j++) {
            const float p = __expf(ssrow[j] - m_new);
            l_i += p;
            const unsigned long long p2 = pack2(p, p);
            const ulonglong2* v2 = (const ulonglong2*)(Vc + j * DK);
#pragma unroll
            for (int c = 0; c < 16; c++) {
                ulonglong2 vv = v2[c];
                o2[2 * c]     = ffma2(p2, vv.x, o2[2 * c]);
                o2[2 * c + 1] = ffma2(p2, vv.y, o2[2 * c + 1]);
            }
        }
        m_i = m_new;
    }

    // ---- epilogue: O = acc / l ----
    const float inv = 1.0f / l_i;
    const unsigned long long inv2 = pack2(inv, inv);
    ulonglong2* Or = (ulonglong2*)(g_X + (size_t)row * DMODEL + h * DK);
#pragma unroll
    for (int c = 0; c < 16; c++)
        Or[c] = make_ulonglong2(fmul2(o2[2 * c], inv2), fmul2(o2[2 * c + 1], inv2));
}

// ---------------------------------------------------------------------------
// Launch
// Inputs (metadata order): q, k, v, w_q, w_k, w_v, w_o, mask
// ---------------------------------------------------------------------------
extern "C" void kernel_launch(void* const* d_in, const int* in_sizes, int n_in,
                              void* d_out, int out_size) {
    const float* q  = (const float*)d_in[0];
    const float* k  = (const float*)d_in[1];
    const float* v  = (const float*)d_in[2];
    const float* wq = (const float*)d_in[3];
    const float* wk = (const float*)d_in[4];
    const float* wv = (const float*)d_in[5];
    const float* wo = (const float*)d_in[6];
    const int* mask = (const int*)d_in[7];
    float* out = (float*)d_out;

    cudaFuncSetAttribute(mha_flash_attn,
                         cudaFuncAttributeMaxDynamicSharedMemorySize,
                         ATT_SMEM_BYTES);

    // Q/K/V projections: grid (N/128, M/128, 3)
    dim3 gqkv(DMODEL / 128, MROWS / 128, 3);
    mha_gemm_qkv<<<gqkv, 256>>>(q, k, v, wq, wk, wv);

    // attention: grid (S/128, B*H)
    dim3 gatt(SEQ / ATT_BM, BATCH * NHEAD);
    mha_flash_attn<<<gatt, 128, ATT_SMEM_BYTES>>>(mask);

    // output projection
    dim3 gout(DMODEL / 128, MROWS / 128, 1);
    mha_gemm_out<<<gout, 256>>>(wo, out);
}

// round 10
// speedup vs baseline: 2.1726x; 2.1726x over previous
#include <cuda_runtime.h>
#include <cuda_bf16.h>

// Problem constants
#define BATCH   2
#define SEQ     2048
#define DMODEL  1024
#define NHEAD   16
#define DK      64
#define MROWS   (BATCH * SEQ)       // 4096

// ---------------------------------------------------------------------------
// Scratch (no allocations allowed -> device globals)
// ---------------------------------------------------------------------------
__device__ float g_Q[MROWS * DMODEL];
__device__ float g_K[MROWS * DMODEL];
__device__ float g_V[MROWS * DMODEL];
__device__ float g_X[MROWS * DMODEL];   // attention output (pre out-proj)

// ---------------------------------------------------------------------------
// Packed fp32x2 helpers (attention kernel)
// ---------------------------------------------------------------------------
__device__ __forceinline__ unsigned long long pack2(float lo, float hi) {
    unsigned long long r;
    asm("mov.b64 %0, {%1, %2};" : "=l"(r) : "f"(lo), "f"(hi));
    return r;
}
__device__ __forceinline__ float2 unpack2(unsigned long long x) {
    float2 r;
    asm("mov.b64 {%0, %1}, %2;" : "=f"(r.x), "=f"(r.y) : "l"(x));
    return r;
}
__device__ __forceinline__ unsigned long long ffma2(unsigned long long a,
                                                    unsigned long long b,
                                                    unsigned long long c) {
    unsigned long long d;
    asm("fma.rn.f32x2 %0, %1, %2, %3;" : "=l"(d) : "l"(a), "l"(b), "l"(c));
    return d;
}
__device__ __forceinline__ unsigned long long fmul2(unsigned long long a,
                                                    unsigned long long b) {
    unsigned long long d;
    asm("mul.rn.f32x2 %0, %1, %2;" : "=l"(d) : "l"(a), "l"(b));
    return d;
}

// ---------------------------------------------------------------------------
// Warp-level tensor core helpers (sm_80-baseline PTX: works on plain sm_103)
// ---------------------------------------------------------------------------
__device__ __forceinline__ unsigned smem_u32(const void* p) {
    return (unsigned)__cvta_generic_to_shared(p);
}
__device__ __forceinline__ void ldmx4(unsigned* r, unsigned addr) {
    asm volatile(
        "ldmatrix.sync.aligned.m8n8.x4.shared.b16 {%0,%1,%2,%3}, [%4];"
        : "=r"(r[0]), "=r"(r[1]), "=r"(r[2]), "=r"(r[3]) : "r"(addr));
}
__device__ __forceinline__ void mma_bf16(float* d, const unsigned* a,
                                         unsigned b0, unsigned b1) {
    asm volatile(
        "mma.sync.aligned.m16n8k16.row.col.f32.bf16.bf16.f32 "
        "{%0,%1,%2,%3}, {%4,%5,%6,%7}, {%8,%9}, {%0,%1,%2,%3};"
        : "+f"(d[0]), "+f"(d[1]), "+f"(d[2]), "+f"(d[3])
        : "r"(a[0]), "r"(a[1]), "r"(a[2]), "r"(a[3]), "r"(b0), "r"(b1));
}

// fp32 pair -> bf16x2 hi + bf16x2 lo (split for precision recovery)
__device__ __forceinline__ void cvt_split2(float x0, float x1,
                                           unsigned& h, unsigned& l) {
    asm("cvt.rn.satfinite.bf16x2.f32 %0, %1, %2;" : "=r"(h) : "f"(x1), "f"(x0));
    float hf0 = __uint_as_float(h << 16);
    float hf1 = __uint_as_float(h & 0xffff0000u);
    float l0 = x0 - hf0;
    float l1 = x1 - hf1;
    asm("cvt.rn.satfinite.bf16x2.f32 %0, %1, %2;" : "=r"(l) : "f"(l1), "f"(l0));
}
__device__ __forceinline__ void split_store(float4 a, float4 b,
                                            char* dst_hi, char* dst_lo) {
    uint4 h, l;
    cvt_split2(a.x, a.y, h.x, l.x);
    cvt_split2(a.z, a.w, h.y, l.y);
    cvt_split2(b.x, b.y, h.z, l.z);
    cvt_split2(b.z, b.w, h.w, l.w);
    *(uint4*)dst_hi = h;
    *(uint4*)dst_lo = l;
}

// ---------------------------------------------------------------------------
// Tensor-core NT GEMM via mma.sync: C[m,n] = sum_k A[m,k] * W[n,k].
// CTA tile 128x128, K staged 64 at a time (single smem buffer, 2 syncs/stage,
// LDG prefetch for stage s+1 issued before the MMA phase of stage s).
// fp32 split into bf16 hi/lo on the fly; 3 MMAs recover ~fp32 precision:
//   C ~= Ah*Bh + Ah*Bl + Al*Bh
// smem layout per tensor: [128 rows][64 bf16] = 128B rows, SW128 swizzle
// (chunk' = chunk ^ (row&7)) -> conflict-free ldmatrix.
// 8 warps = 2(m) x 4(n); warp tile 64x32 = 4 m16-frags x 4 n8-frags.
// ---------------------------------------------------------------------------
#define GK_STAGES 16
#define GK_TILE_BYTES (128 * 64 * 2)            // 16384 per tensor-half
#define GK_BUF_BYTES (4 * GK_TILE_BYTES)        // Ah, Al, Bh, Bl = 64 KB
#define GEMM_SMEM (GK_BUF_BYTES + 1024)

__device__ __forceinline__ void gemm_tc_body(const float* __restrict__ A,
                                             const float* __restrict__ W,
                                             float* __restrict__ C) {
    extern __shared__ char dyn_raw[];
    char* dynb = (char*)(((unsigned long long)(size_t)dyn_raw + 1023ull) &
                         ~1023ull);

    const int tid = threadIdx.x;
    const int wid = tid >> 5;
    const int lane = tid & 31;
    const int m0 = blockIdx.y * 128;
    const int n0 = blockIdx.x * 128;

    const unsigned smem_base = smem_u32(dynb);
    const unsigned sA_h = smem_base;
    const unsigned sA_l = smem_base + GK_TILE_BYTES;
    const unsigned sB_h = smem_base + 2 * GK_TILE_BYTES;
    const unsigned sB_l = smem_base + 3 * GK_TILE_BYTES;

    const float4* A4 = (const float4*)A;
    const float4* W4 = (const float4*)W;

    // staging mapping: thread handles rows rb0+32i (i=0..3), 16B-chunk cc
    const int rb0 = tid >> 3;     // 0..31
    const int cc  = tid & 7;      // chunk within 64-elem k-slab

    // mma addressing (per lane, loop-invariant parts)
    const int wm = (wid >> 2) * 64;
    const int wn = (wid & 3) * 32;
    const int arow = lane & 15;
    const unsigned axor = (unsigned)((arow & 7) << 4);
    const unsigned ahi = (unsigned)(lane >> 4);            // 0/1
    const int brow = (lane & 7) + ((lane >> 4) << 3);      // 0..15
    const unsigned bxor = (unsigned)((brow & 7) << 4);
    const unsigned bhi = (unsigned)((lane >> 3) & 1);

    float d[4][4][4];
#pragma unroll
    for (int i = 0; i < 4; i++)
#pragma unroll
        for (int j = 0; j < 4; j++)
#pragma unroll
            for (int c = 0; c < 4; c++) d[i][j][c] = 0.0f;

    float4 ra[4][2], rb_[4][2];

#define GK_LDG(s)                                                        \
    do {                                                                 \
        _Pragma("unroll")                                                \
        for (int i = 0; i < 4; i++) {                                    \
            const int r = rb0 + 32 * i;                                  \
            const size_t ga = (size_t)(m0 + r) * 256 + (s) * 16 + cc * 2;\
            const size_t gb = (size_t)(n0 + r) * 256 + (s) * 16 + cc * 2;\
            ra[i][0]  = A4[ga];     ra[i][1]  = A4[ga + 1];              \
            rb_[i][0] = W4[gb];     rb_[i][1] = W4[gb + 1];              \
        }                                                                \
    } while (0)

    GK_LDG(0);

    for (int s = 0; s < GK_STAGES; s++) {
        // ---- stage: convert fp32 -> bf16 hi/lo, swizzled STS ----
        {
            char* Ah = dynb;
            char* Al = dynb + GK_TILE_BYTES;
            char* Bh = dynb + 2 * GK_TILE_BYTES;
            char* Bl = dynb + 3 * GK_TILE_BYTES;
#pragma unroll
            for (int i = 0; i < 4; i++) {
                const int r = rb0 + 32 * i;
                const unsigned off = (unsigned)(r * 128 + cc * 16);
                const unsigned sw = off ^ ((off >> 3) & 0x70);
                split_store(ra[i][0], ra[i][1], Ah + sw, Al + sw);
                split_store(rb_[i][0], rb_[i][1], Bh + sw, Bl + sw);
            }
        }
        __syncthreads();

        if (s + 1 < GK_STAGES) GK_LDG(s + 1);   // in flight during MMA phase

        // ---- MMA phase: 4 k16-steps over the 64-wide slab ----
#pragma unroll
        for (int ks = 0; ks < 4; ks++) {
            unsigned bh[2][4], bl[2][4];
#pragma unroll
            for (int j2 = 0; j2 < 2; j2++) {
                const unsigned roff =
                    (unsigned)(wn + 16 * j2 + brow) * 128 +
                    ((((unsigned)(2 * ks) + bhi) << 4) ^ bxor);
                ldmx4(bh[j2], sB_h + roff);
                ldmx4(bl[j2], sB_l + roff);
            }
#pragma unroll
            for (int i = 0; i < 4; i++) {
                const unsigned aoff =
                    (unsigned)(wm + 16 * i + arow) * 128 +
                    ((((unsigned)(2 * ks) + ahi) << 4) ^ axor);
                unsigned ah[4], al[4];
                ldmx4(ah, sA_h + aoff);
                ldmx4(al, sA_l + aoff);
#pragma unroll
                for (int j = 0; j < 4; j++) {
                    const unsigned b0h = bh[j >> 1][(j & 1) * 2];
                    const unsigned b1h = bh[j >> 1][(j & 1) * 2 + 1];
                    const unsigned b0l = bl[j >> 1][(j & 1) * 2];
                    const unsigned b1l = bl[j >> 1][(j & 1) * 2 + 1];
                    mma_bf16(d[i][j], ah, b0h, b1h);
                    mma_bf16(d[i][j], ah, b0l, b1l);
                    mma_bf16(d[i][j], al, b0h, b1h);
                }
            }
        }
        __syncthreads();   // MMA reads done; next stage may overwrite smem
    }
#undef GK_LDG

    // ---- epilogue: fragment -> gmem (two float2 per frag) ----
    float* Cbase = C + (size_t)(m0 + wm + (lane >> 2)) * 1024 +
                   n0 + wn + (lane & 3) * 2;
#pragma unroll
    for (int i = 0; i < 4; i++)
#pragma unroll
        for (int j = 0; j < 4; j++) {
            *(float2*)(Cbase + (size_t)(16 * i) * 1024 + 8 * j) =
                make_float2(d[i][j][0], d[i][j][1]);
            *(float2*)(Cbase + (size_t)(16 * i + 8) * 1024 + 8 * j) =
                make_float2(d[i][j][2], d[i][j][3]);
        }
}

__global__ void __launch_bounds__(256, 1)
mha_gemm_qkv(const float* __restrict__ q, const float* __restrict__ k,
             const float* __restrict__ v, const float* __restrict__ wq,
             const float* __restrict__ wk, const float* __restrict__ wv) {
    const int z = blockIdx.z;
    const float* A = (z == 0) ? q : (z == 1) ? k : v;
    const float* W = (z == 0) ? wq : (z == 1) ? wk : wv;
    float* C = (z == 0) ? g_Q : (z == 1) ? g_K : g_V;
    gemm_tc_body(A, W, C);
}

__global__ void __launch_bounds__(256, 1)
mha_gemm_out(const float* __restrict__ wo, float* __restrict__ out) {
    gemm_tc_body(g_X, wo, out);
}

// ---------------------------------------------------------------------------
// Flash attention (proven R4 version): CTA = 128 query rows x one
// (batch, head); 128 threads, thread t owns row q0+t. K/V tiles (64x64) in
// smem read as broadcast ulonglong2; scores in smem (stride 65).
// ---------------------------------------------------------------------------
#define ATT_BM 128
#define ATT_BN 64
#define ATT_SS_STRIDE 65
#define ATT_SMEM_BYTES ((2 * ATT_BN * DK + ATT_BM * ATT_SS_STRIDE) * 4)

__global__ void __launch_bounds__(128)
mha_flash_attn(const int* __restrict__ mask) {
    extern __shared__ float smf[];
    float* Ks = smf;                       // [64][64]
    float* Vs = smf + ATT_BN * DK;         // [64][64]
    float* Ss = smf + 2 * ATT_BN * DK;     // [128][65]

    const int t  = threadIdx.x;
    const int q0 = blockIdx.x * ATT_BM;
    const int bh = blockIdx.y;
    const int b  = bh >> 4;
    const int h  = bh & 15;
    const int row = b * SEQ + q0 + t;      // row into [B*S, D]

    unsigned long long q2[32];
    {
        const ulonglong2* Qr =
            (const ulonglong2*)(g_Q + (size_t)row * DMODEL + h * DK);
#pragma unroll
        for (int i = 0; i < 16; i++) {
            ulonglong2 tq = Qr[i];
            q2[2 * i]     = tq.x;
            q2[2 * i + 1] = tq.y;
        }
    }
    unsigned long long o2[32];
#pragma unroll
    for (int i = 0; i < 32; i++) o2[i] = 0ull;

    float m_i = -1e30f;
    float l_i = 0.0f;

    const int* mrow = mask + ((size_t)b * SEQ + (q0 + t)) * SEQ;
    float* ssrow = Ss + t * ATT_SS_STRIDE;

    const float4* K4base = (const float4*)g_K;
    const float4* V4base = (const float4*)g_V;

    for (int j0 = 0; j0 < SEQ; j0 += ATT_BN) {
        {
            const size_t base = (size_t)(b * SEQ + j0) * 256 + h * 16;
#pragma unroll
            for (int it = 0; it < 8; it++) {
                const int i = t + it * 128;
                const int r = i >> 4, c = i & 15;
                ((float4*)Ks)[i] = K4base[base + (size_t)r * 256 + c];
                ((float4*)Vs)[i] = V4base[base + (size_t)r * 256 + c];
            }
        }
        __syncthreads();

        float tmax = -1e30f;
#pragma unroll 2
        for (int j4 = 0; j4 < ATT_BN / 4; j4++) {
            const int4 mv = *(const int4*)(mrow + j0 + j4 * 4);
            const int mvals[4] = {mv.x, mv.y, mv.z, mv.w};
#pragma unroll
            for (int jj = 0; jj < 4; jj++) {
                const int j = j4 * 4 + jj;
                const ulonglong2* k2 = (const ulonglong2*)(Ks + j * DK);
                unsigned long long acc0 = 0ull, acc1 = 0ull;
#pragma unroll
                for (int c = 0; c < 16; c++) {
                    ulonglong2 kv = k2[c];
                    acc0 = ffma2(q2[2 * c],     kv.x, acc0);
                    acc1 = ffma2(q2[2 * c + 1], kv.y, acc1);
                }
                float2 a0 = unpack2(acc0);
                float2 a1 = unpack2(acc1);
                float s = (a0.x + a0.y + a1.x + a1.y) * 0.125f;
                if (mvals[jj] == 0) s = -1e9f;
                ssrow[j] = s;
                tmax = fmaxf(tmax, s);
            }
        }

        const float m_new = fmaxf(m_i, tmax);
        const float alpha = __expf(m_i - m_new);
        l_i *= alpha;
        {
            const unsigned long long a2 = pack2(alpha, alpha);
#pragma unroll
            for (int c = 0; c < 32; c++) o2[c] = fmul2(o2[c], a2);
        }

        for (int j = 0; j < ATT_BN; j++) {
            const float p = __expf(ssrow[j] - m_new);
            l_i += p;
            const unsigned long long p2 = pack2(p, p);
            const ulonglong2* v2 = (const ulonglong2*)(Vs + j * DK);
#pragma unroll
            for (int c = 0; c < 16; c++) {
                ulonglong2 vv = v2[c];
                o2[2 * c]     = ffma2(p2, vv.x, o2[2 * c]);
                o2[2 * c + 1] = ffma2(p2, vv.y, o2[2 * c + 1]);
            }
        }
        m_i = m_new;
        __syncthreads();
    }

    const float inv = 1.0f / l_i;
    const unsigned long long inv2 = pack2(inv, inv);
    unsigned long long* Or =
        (unsigned long long*)(g_X + (size_t)row * DMODEL + h * DK);
#pragma unroll
    for (int c = 0; c < 32; c++) Or[c] = fmul2(o2[c], inv2);
}

// ---------------------------------------------------------------------------
// Launch
// Inputs (metadata order): q, k, v, w_q, w_k, w_v, w_o, mask
// ---------------------------------------------------------------------------
extern "C" void kernel_launch(void* const* d_in, const int* in_sizes, int n_in,
                              void* d_out, int out_size) {
    const float* q  = (const float*)d_in[0];
    const float* k  = (const float*)d_in[1];
    const float* v  = (const float*)d_in[2];
    const float* wq = (const float*)d_in[3];
    const float* wk = (const float*)d_in[4];
    const float* wv = (const float*)d_in[5];
    const float* wo = (const float*)d_in[6];
    const int* mask = (const int*)d_in[7];
    float* out = (float*)d_out;

    cudaFuncSetAttribute(mha_gemm_qkv,
                         cudaFuncAttributeMaxDynamicSharedMemorySize, GEMM_SMEM);
    cudaFuncSetAttribute(mha_gemm_out,
                         cudaFuncAttributeMaxDynamicSharedMemorySize, GEMM_SMEM);
    cudaFuncSetAttribute(mha_flash_attn,
                         cudaFuncAttributeMaxDynamicSharedMemorySize,
                         ATT_SMEM_BYTES);

    // Q/K/V projections: grid (N/128, M/128, 3), tensor-core GEMM
    dim3 gqkv(DMODEL / 128, MROWS / 128, 3);
    mha_gemm_qkv<<<gqkv, 256, GEMM_SMEM>>>(q, k, v, wq, wk, wv);

    // attention: grid (S/128, B*H)
    dim3 gatt(SEQ / ATT_BM, BATCH * NHEAD);
    mha_flash_attn<<<gatt, 128, ATT_SMEM_BYTES>>>(mask);

    // output projection
    dim3 gout(DMODEL / 128, MROWS / 128, 1);
    mha_gemm_out<<<gout, 256, GEMM_SMEM>>>(wo, out);
}

// round 11
// speedup vs baseline: 4.5972x; 2.1160x over previous
#include <cuda_runtime.h>
#include <cuda_bf16.h>

// Problem constants
#define BATCH   2
#define SEQ     2048
#define DMODEL  1024
#define NHEAD   16
#define DK      64
#define MROWS   (BATCH * SEQ)       // 4096

// ---------------------------------------------------------------------------
// Scratch (no allocations allowed -> device globals)
// ---------------------------------------------------------------------------
__device__ float g_Q[MROWS * DMODEL];
__device__ float g_K[MROWS * DMODEL];
__device__ float g_V[MROWS * DMODEL];
__device__ float g_X[MROWS * DMODEL];   // attention output (pre out-proj)

// ---------------------------------------------------------------------------
// Warp-level tensor core helpers (sm_80-baseline PTX: works on plain sm_103)
// ---------------------------------------------------------------------------
__device__ __forceinline__ unsigned smem_u32(const void* p) {
    return (unsigned)__cvta_generic_to_shared(p);
}
__device__ __forceinline__ void ldmx4(unsigned* r, unsigned addr) {
    asm volatile(
        "ldmatrix.sync.aligned.m8n8.x4.shared.b16 {%0,%1,%2,%3}, [%4];"
        : "=r"(r[0]), "=r"(r[1]), "=r"(r[2]), "=r"(r[3]) : "r"(addr));
}
__device__ __forceinline__ void ldmx4t(unsigned* r, unsigned addr) {
    asm volatile(
        "ldmatrix.sync.aligned.m8n8.x4.trans.shared.b16 {%0,%1,%2,%3}, [%4];"
        : "=r"(r[0]), "=r"(r[1]), "=r"(r[2]), "=r"(r[3]) : "r"(addr));
}
__device__ __forceinline__ void mma_bf16(float* d, const unsigned* a,
                                         unsigned b0, unsigned b1) {
    asm volatile(
        "mma.sync.aligned.m16n8k16.row.col.f32.bf16.bf16.f32 "
        "{%0,%1,%2,%3}, {%4,%5,%6,%7}, {%8,%9}, {%0,%1,%2,%3};"
        : "+f"(d[0]), "+f"(d[1]), "+f"(d[2]), "+f"(d[3])
        : "r"(a[0]), "r"(a[1]), "r"(a[2]), "r"(a[3]), "r"(b0), "r"(b1));
}

// fp32 pair -> bf16x2 hi + bf16x2 lo (split for precision recovery)
__device__ __forceinline__ void cvt_split2(float x0, float x1,
                                           unsigned& h, unsigned& l) {
    asm("cvt.rn.satfinite.bf16x2.f32 %0, %1, %2;" : "=r"(h) : "f"(x1), "f"(x0));
    float hf0 = __uint_as_float(h << 16);
    float hf1 = __uint_as_float(h & 0xffff0000u);
    float l0 = x0 - hf0;
    float l1 = x1 - hf1;
    asm("cvt.rn.satfinite.bf16x2.f32 %0, %1, %2;" : "=r"(l) : "f"(l1), "f"(l0));
}
__device__ __forceinline__ void split_store(float4 a, float4 b,
                                            char* dst_hi, char* dst_lo) {
    uint4 h, l;
    cvt_split2(a.x, a.y, h.x, l.x);
    cvt_split2(a.z, a.w, h.y, l.y);
    cvt_split2(b.x, b.y, h.z, l.z);
    cvt_split2(b.z, b.w, h.w, l.w);
    *(uint4*)dst_hi = h;
    *(uint4*)dst_lo = l;
}

// ---------------------------------------------------------------------------
// Tensor-core NT GEMM via mma.sync (verified R10, unchanged):
// C[m,n] = sum_k A[m,k]*W[n,k]; CTA 128x128, K staged 64/stage.
// ---------------------------------------------------------------------------
#define GK_STAGES 16
#define GK_TILE_BYTES (128 * 64 * 2)            // 16384 per tensor-half
#define GK_BUF_BYTES (4 * GK_TILE_BYTES)        // Ah, Al, Bh, Bl = 64 KB
#define GEMM_SMEM (GK_BUF_BYTES + 1024)

__device__ __forceinline__ void gemm_tc_body(const float* __restrict__ A,
                                             const float* __restrict__ W,
                                             float* __restrict__ C) {
    extern __shared__ char dyn_raw[];
    char* dynb = (char*)(((unsigned long long)(size_t)dyn_raw + 1023ull) &
                         ~1023ull);

    const int tid = threadIdx.x;
    const int wid = tid >> 5;
    const int lane = tid & 31;
    const int m0 = blockIdx.y * 128;
    const int n0 = blockIdx.x * 128;

    const unsigned smem_base = smem_u32(dynb);
    const unsigned sA_h = smem_base;
    const unsigned sA_l = smem_base + GK_TILE_BYTES;
    const unsigned sB_h = smem_base + 2 * GK_TILE_BYTES;
    const unsigned sB_l = smem_base + 3 * GK_TILE_BYTES;

    const float4* A4 = (const float4*)A;
    const float4* W4 = (const float4*)W;

    const int rb0 = tid >> 3;     // 0..31
    const int cc  = tid & 7;

    const int wm = (wid >> 2) * 64;
    const int wn = (wid & 3) * 32;
    const int arow = lane & 15;
    const unsigned axor = (unsigned)((arow & 7) << 4);
    const unsigned ahi = (unsigned)(lane >> 4);
    const int brow = (lane & 7) + ((lane >> 4) << 3);
    const unsigned bxor = (unsigned)((brow & 7) << 4);
    const unsigned bhi = (unsigned)((lane >> 3) & 1);

    float d[4][4][4];
#pragma unroll
    for (int i = 0; i < 4; i++)
#pragma unroll
        for (int j = 0; j < 4; j++)
#pragma unroll
            for (int c = 0; c < 4; c++) d[i][j][c] = 0.0f;

    float4 ra[4][2], rb_[4][2];

#define GK_LDG(s)                                                        \
    do {                                                                 \
        _Pragma("unroll")                                                \
        for (int i = 0; i < 4; i++) {                                    \
            const int r = rb0 + 32 * i;                                  \
            const size_t ga = (size_t)(m0 + r) * 256 + (s) * 16 + cc * 2;\
            const size_t gb = (size_t)(n0 + r) * 256 + (s) * 16 + cc * 2;\
            ra[i][0]  = A4[ga];     ra[i][1]  = A4[ga + 1];              \
            rb_[i][0] = W4[gb];     rb_[i][1] = W4[gb + 1];              \
        }                                                                \
    } while (0)

    GK_LDG(0);

    for (int s = 0; s < GK_STAGES; s++) {
        {
            char* Ah = dynb;
            char* Al = dynb + GK_TILE_BYTES;
            char* Bh = dynb + 2 * GK_TILE_BYTES;
            char* Bl = dynb + 3 * GK_TILE_BYTES;
#pragma unroll
            for (int i = 0; i < 4; i++) {
                const int r = rb0 + 32 * i;
                const unsigned off = (unsigned)(r * 128 + cc * 16);
                const unsigned sw = off ^ ((off >> 3) & 0x70);
                split_store(ra[i][0], ra[i][1], Ah + sw, Al + sw);
                split_store(rb_[i][0], rb_[i][1], Bh + sw, Bl + sw);
            }
        }
        __syncthreads();

        if (s + 1 < GK_STAGES) GK_LDG(s + 1);

#pragma unroll
        for (int ks = 0; ks < 4; ks++) {
            unsigned bh[2][4], bl[2][4];
#pragma unroll
            for (int j2 = 0; j2 < 2; j2++) {
                const unsigned roff =
                    (unsigned)(wn + 16 * j2 + brow) * 128 +
                    ((((unsigned)(2 * ks) + bhi) << 4) ^ bxor);
                ldmx4(bh[j2], sB_h + roff);
                ldmx4(bl[j2], sB_l + roff);
            }
#pragma unroll
            for (int i = 0; i < 4; i++) {
                const unsigned aoff =
                    (unsigned)(wm + 16 * i + arow) * 128 +
                    ((((unsigned)(2 * ks) + ahi) << 4) ^ axor);
                unsigned ah[4], al[4];
                ldmx4(ah, sA_h + aoff);
                ldmx4(al, sA_l + aoff);
#pragma unroll
                for (int j = 0; j < 4; j++) {
                    const unsigned b0h = bh[j >> 1][(j & 1) * 2];
                    const unsigned b1h = bh[j >> 1][(j & 1) * 2 + 1];
                    const unsigned b0l = bl[j >> 1][(j & 1) * 2];
                    const unsigned b1l = bl[j >> 1][(j & 1) * 2 + 1];
                    mma_bf16(d[i][j], ah, b0h, b1h);
                    mma_bf16(d[i][j], ah, b0l, b1l);
                    mma_bf16(d[i][j], al, b0h, b1h);
                }
            }
        }
        __syncthreads();
    }
#undef GK_LDG

    float* Cbase = C + (size_t)(m0 + wm + (lane >> 2)) * 1024 +
                   n0 + wn + (lane & 3) * 2;
#pragma unroll
    for (int i = 0; i < 4; i++)
#pragma unroll
        for (int j = 0; j < 4; j++) {
            *(float2*)(Cbase + (size_t)(16 * i) * 1024 + 8 * j) =
                make_float2(d[i][j][0], d[i][j][1]);
            *(float2*)(Cbase + (size_t)(16 * i + 8) * 1024 + 8 * j) =
                make_float2(d[i][j][2], d[i][j][3]);
        }
}

__global__ void __launch_bounds__(256, 1)
mha_gemm_qkv(const float* __restrict__ q, const float* __restrict__ k,
             const float* __restrict__ v, const float* __restrict__ wq,
             const float* __restrict__ wk, const float* __restrict__ wv) {
    const int z = blockIdx.z;
    const float* A = (z == 0) ? q : (z == 1) ? k : v;
    const float* W = (z == 0) ? wq : (z == 1) ? wk : wv;
    float* C = (z == 0) ? g_Q : (z == 1) ? g_K : g_V;
    gemm_tc_body(A, W, C);
}

__global__ void __launch_bounds__(256, 1)
mha_gemm_out(const float* __restrict__ wo, float* __restrict__ out) {
    gemm_tc_body(g_X, wo, out);
}

// ---------------------------------------------------------------------------
// Tensor-core flash attention.
// CTA = 128 query rows x one (batch, head); 256 threads = 8 warps, warp w
// owns rows 16w..16w+15.  BN = 64 keys per tile.
// Q converted once to bf16 hi/lo fragments held in registers.
// K/V tiles converted fp32->bf16 hi/lo into SW128 smem each iteration.
// S = Q.K^T via 3-way split MMA (fp32-class precision); softmax on fragments;
// P repacked in registers (C-frag == A-frag ownership) with hi/lo split;
// O += P.V via 3-way split MMA with ldmatrix.trans B-fragments of V.
// ---------------------------------------------------------------------------
#define ATT_BM 128
#define ATT_BN 64
#define ATT_TILE_B (ATT_BN * 128)        // 8192 B: 64 rows x 128B (bf16)
#define ATT_SMEM (4 * ATT_TILE_B + 1024) // Kh,Kl,Vh,Vl + align slack

__global__ void __launch_bounds__(256, 1)
mha_flash_attn_tc(const int* __restrict__ mask) {
    extern __shared__ char att_raw[];
    char* base = (char*)(((unsigned long long)(size_t)att_raw + 1023ull) &
                         ~1023ull);
    const unsigned sKh = smem_u32(base);
    const unsigned sKl = sKh + ATT_TILE_B;
    const unsigned sVh = sKh + 2 * ATT_TILE_B;
    const unsigned sVl = sKh + 3 * ATT_TILE_B;
    // Q staging (transient): hi at sKh (16KB), lo at sVh (16KB)

    const int tid = threadIdx.x;
    const int wid = tid >> 5;
    const int lane = tid & 31;
    const int q0 = blockIdx.x * ATT_BM;
    const int bh = blockIdx.y;
    const int b = bh >> 4;
    const int h = bh & 15;

    const float4* Q4 = (const float4*)g_Q;
    const float4* K4 = (const float4*)g_K;
    const float4* V4 = (const float4*)g_V;

    // ---- stage Q (128 rows x 64 cols) as bf16 hi/lo, swizzled ----
#pragma unroll
    for (int i = 0; i < 4; i++) {
        const int idx = tid + 256 * i;          // 0..1023
        const int r = idx >> 3;
        const int cc = idx & 7;
        const size_t g = (size_t)(b * SEQ + q0 + r) * 256 + h * 16 + cc * 2;
        float4 x0 = Q4[g], x1 = Q4[g + 1];
        const unsigned off = (unsigned)(r * 128 + ((cc ^ (r & 7)) << 4));
        split_store(x0, x1, base + off, base + 2 * ATT_TILE_B + off);
    }
    __syncthreads();

    // ---- Q fragments (held in registers for whole kernel) ----
    unsigned qh[4][4], ql[4][4];
    {
        const int arow = lane & 15;
        const unsigned ahi = (unsigned)(lane >> 4);
        const int row = 16 * wid + arow;
#pragma unroll
        for (int kk = 0; kk < 4; kk++) {
            const unsigned ch = 2 * (unsigned)kk + ahi;
            const unsigned off =
                (unsigned)(row * 128) + ((ch ^ (unsigned)(row & 7)) << 4);
            ldmx4(qh[kk], sKh + off);
            ldmx4(ql[kk], sVh + off);
        }
    }
    __syncthreads();   // Q staging buffers now reusable for K/V

    float o[8][4];
#pragma unroll
    for (int j = 0; j < 8; j++)
#pragma unroll
        for (int e = 0; e < 4; e++) o[j][e] = 0.0f;
    float m0 = -1e30f, m1 = -1e30f, l0 = 0.0f, l1 = 0.0f;

    const int grow = q0 + 16 * wid + (lane >> 2);
    const int* mrow0 = mask + ((size_t)b * SEQ + grow) * SEQ;
    const int* mrow1 = mrow0 + 8 * SEQ;

    const int brow = (lane & 7) + ((lane >> 4) << 3);
    const unsigned bxor = (unsigned)((brow & 7) << 4);
    const unsigned bhi = (unsigned)((lane >> 3) & 1);
    const int vtt = lane >> 3;                 // trans tile select
    const int vrow_lo = ((vtt & 1) << 3) + (lane & 7);
    const unsigned vch_add = (unsigned)(vtt >> 1);

    for (int n = 0; n < SEQ / ATT_BN; n++) {
        const int j0 = n * ATT_BN;
        if (n) __syncthreads();                 // prev tile reads done

        // ---- stage K/V tile (64 rows x 64 cols each) ----
#pragma unroll
        for (int i = 0; i < 2; i++) {
            const int idx = tid + 256 * i;      // 0..511
            const int r = idx >> 3;
            const int cc = idx & 7;
            const size_t g = (size_t)(b * SEQ + j0 + r) * 256 + h * 16 + cc * 2;
            float4 k0 = K4[g], k1 = K4[g + 1];
            float4 v0 = V4[g], v1 = V4[g + 1];
            const unsigned off = (unsigned)(r * 128 + ((cc ^ (r & 7)) << 4));
            split_store(k0, k1, base + off, base + ATT_TILE_B + off);
            split_store(v0, v1, base + 2 * ATT_TILE_B + off,
                        base + 3 * ATT_TILE_B + off);
        }
        __syncthreads();

        // ---- S = Q.K^T (3-way split) ----
        float c[8][4];
#pragma unroll
        for (int j = 0; j < 8; j++)
#pragma unroll
            for (int e = 0; e < 4; e++) c[j][e] = 0.0f;

#pragma unroll
        for (int ks = 0; ks < 4; ks++) {
#pragma unroll
            for (int j2 = 0; j2 < 4; j2++) {
                const int kr = 16 * j2 + brow;
                const unsigned off = (unsigned)(kr * 128) +
                    ((((unsigned)(2 * ks) + bhi) << 4) ^ bxor);
                unsigned kbh[4], kbl[4];
                ldmx4(kbh, sKh + off);
                ldmx4(kbl, sKl + off);
#pragma unroll
                for (int jj = 0; jj < 2; jj++) {
                    const int j = 2 * j2 + jj;
                    mma_bf16(c[j], qh[ks], kbh[2 * jj], kbh[2 * jj + 1]);
                    mma_bf16(c[j], qh[ks], kbl[2 * jj], kbl[2 * jj + 1]);
                    mma_bf16(c[j], ql[ks], kbh[2 * jj], kbh[2 * jj + 1]);
                }
            }
        }

        // ---- scale + mask ----
        const int mcol = j0 + 2 * (lane & 3);
#pragma unroll
        for (int j = 0; j < 8; j++) {
            const int2 mv0 = *(const int2*)(mrow0 + mcol + 8 * j);
            const int2 mv1 = *(const int2*)(mrow1 + mcol + 8 * j);
            c[j][0] = mv0.x ? c[j][0] * 0.125f : -1e9f;
            c[j][1] = mv0.y ? c[j][1] * 0.125f : -1e9f;
            c[j][2] = mv1.x ? c[j][2] * 0.125f : -1e9f;
            c[j][3] = mv1.y ? c[j][3] * 0.125f : -1e9f;
        }

        // ---- row max (quad shuffle reduce) ----
        float t0 = -1e30f, t1 = -1e30f;
#pragma unroll
        for (int j = 0; j < 8; j++) {
            t0 = fmaxf(t0, fmaxf(c[j][0], c[j][1]));
            t1 = fmaxf(t1, fmaxf(c[j][2], c[j][3]));
        }
        t0 = fmaxf(t0, __shfl_xor_sync(0xffffffffu, t0, 1));
        t0 = fmaxf(t0, __shfl_xor_sync(0xffffffffu, t0, 2));
        t1 = fmaxf(t1, __shfl_xor_sync(0xffffffffu, t1, 1));
        t1 = fmaxf(t1, __shfl_xor_sync(0xffffffffu, t1, 2));

        const float mn0 = fmaxf(m0, t0);
        const float mn1 = fmaxf(m1, t1);
        const float al0 = __expf(m0 - mn0);
        const float al1 = __expf(m1 - mn1);
        m0 = mn0; m1 = mn1;
        l0 *= al0; l1 *= al1;
#pragma unroll
        for (int j = 0; j < 8; j++) {
            o[j][0] *= al0; o[j][1] *= al0;
            o[j][2] *= al1; o[j][3] *= al1;
        }

        // ---- exponentiate, accumulate row sums ----
#pragma unroll
        for (int j = 0; j < 8; j++) {
            c[j][0] = __expf(c[j][0] - m0);
            c[j][1] = __expf(c[j][1] - m0);
            c[j][2] = __expf(c[j][2] - m1);
            c[j][3] = __expf(c[j][3] - m1);
            l0 += c[j][0] + c[j][1];
            l1 += c[j][2] + c[j][3];
        }

        // ---- O += P.V (register repack, 3-way split) ----
#pragma unroll
        for (int kk = 0; kk < 4; kk++) {
            unsigned pah[4], pal[4];
            cvt_split2(c[2 * kk][0],     c[2 * kk][1],     pah[0], pal[0]);
            cvt_split2(c[2 * kk][2],     c[2 * kk][3],     pah[1], pal[1]);
            cvt_split2(c[2 * kk + 1][0], c[2 * kk + 1][1], pah[2], pal[2]);
            cvt_split2(c[2 * kk + 1][2], c[2 * kk + 1][3], pah[3], pal[3]);
#pragma unroll
            for (int j2 = 0; j2 < 4; j2++) {
                const int vr = 16 * kk + vrow_lo;
                const unsigned ch = 2 * (unsigned)j2 + vch_add;
                const unsigned off = (unsigned)(vr * 128) +
                    ((ch ^ (unsigned)(vr & 7)) << 4);
                unsigned vbh[4], vbl[4];
                ldmx4t(vbh, sVh + off);
                ldmx4t(vbl, sVl + off);
#pragma unroll
                for (int jj = 0; jj < 2; jj++) {
                    const int j = 2 * j2 + jj;
                    mma_bf16(o[j], pah, vbh[2 * jj], vbh[2 * jj + 1]);
                    mma_bf16(o[j], pah, vbl[2 * jj], vbl[2 * jj + 1]);
                    mma_bf16(o[j], pal, vbh[2 * jj], vbh[2 * jj + 1]);
                }
            }
        }
    }

    // ---- finalize: full row sums, normalize, write g_X ----
    l0 += __shfl_xor_sync(0xffffffffu, l0, 1);
    l0 += __shfl_xor_sync(0xffffffffu, l0, 2);
    l1 += __shfl_xor_sync(0xffffffffu, l1, 1);
    l1 += __shfl_xor_sync(0xffffffffu, l1, 2);
    const float inv0 = 1.0f / l0;
    const float inv1 = 1.0f / l1;

    float* X0 = g_X + (size_t)(b * SEQ + grow) * DMODEL + h * DK +
                2 * (lane & 3);
    float* X1 = X0 + (size_t)8 * DMODEL;
#pragma unroll
    for (int j = 0; j < 8; j++) {
        *(float2*)(X0 + 8 * j) = make_float2(o[j][0] * inv0, o[j][1] * inv0);
        *(float2*)(X1 + 8 * j) = make_float2(o[j][2] * inv1, o[j][3] * inv1);
    }
}

// ---------------------------------------------------------------------------
// Launch
// Inputs (metadata order): q, k, v, w_q, w_k, w_v, w_o, mask
// ---------------------------------------------------------------------------
extern "C" void kernel_launch(void* const* d_in, const int* in_sizes, int n_in,
                              void* d_out, int out_size) {
    const float* q  = (const float*)d_in[0];
    const float* k  = (const float*)d_in[1];
    const float* v  = (const float*)d_in[2];
    const float* wq = (const float*)d_in[3];
    const float* wk = (const float*)d_in[4];
    const float* wv = (const float*)d_in[5];
    const float* wo = (const float*)d_in[6];
    const int* mask = (const int*)d_in[7];
    float* out = (float*)d_out;

    cudaFuncSetAttribute(mha_gemm_qkv,
                         cudaFuncAttributeMaxDynamicSharedMemorySize, GEMM_SMEM);
    cudaFuncSetAttribute(mha_gemm_out,
                         cudaFuncAttributeMaxDynamicSharedMemorySize, GEMM_SMEM);
    cudaFuncSetAttribute(mha_flash_attn_tc,
                         cudaFuncAttributeMaxDynamicSharedMemorySize, ATT_SMEM);

    // Q/K/V projections: grid (N/128, M/128, 3), tensor-core GEMM
    dim3 gqkv(DMODEL / 128, MROWS / 128, 3);
    mha_gemm_qkv<<<gqkv, 256, GEMM_SMEM>>>(q, k, v, wq, wk, wv);

    // attention: grid (S/128, B*H), tensor-core flash attention
    dim3 gatt(SEQ / ATT_BM, BATCH * NHEAD);
    mha_flash_attn_tc<<<gatt, 256, ATT_SMEM>>>(mask);

    // output projection
    dim3 gout(DMODEL / 128, MROWS / 128, 1);
    mha_gemm_out<<<gout, 256, GEMM_SMEM>>>(wo, out);
}

// round 12
// speedup vs baseline: 5.4401x; 1.1834x over previous
#include <cuda_runtime.h>
#include <cuda_bf16.h>

// Problem constants
#define BATCH   2
#define SEQ     2048
#define DMODEL  1024
#define NHEAD   16
#define DK      64
#define MROWS   (BATCH * SEQ)       // 4096
#define DM2     (DMODEL / 2)        // u32 (bf16x2) per row

// ---------------------------------------------------------------------------
// Scratch: Q/K/V/X stored pre-split as bf16 hi/lo (u32 = bf16x2 pair)
// ---------------------------------------------------------------------------
__device__ unsigned g_Qh[MROWS * DM2], g_Ql[MROWS * DM2];
__device__ unsigned g_Kh[MROWS * DM2], g_Kl[MROWS * DM2];
__device__ unsigned g_Vh[MROWS * DM2], g_Vl[MROWS * DM2];
__device__ unsigned g_Xh[MROWS * DM2], g_Xl[MROWS * DM2];

// ---------------------------------------------------------------------------
// Warp-level tensor core helpers (sm_80-baseline PTX: works on plain sm_103)
// ---------------------------------------------------------------------------
__device__ __forceinline__ unsigned smem_u32(const void* p) {
    return (unsigned)__cvta_generic_to_shared(p);
}
__device__ __forceinline__ void ldmx4(unsigned* r, unsigned addr) {
    asm volatile(
        "ldmatrix.sync.aligned.m8n8.x4.shared.b16 {%0,%1,%2,%3}, [%4];"
        : "=r"(r[0]), "=r"(r[1]), "=r"(r[2]), "=r"(r[3]) : "r"(addr));
}
__device__ __forceinline__ void ldmx4t(unsigned* r, unsigned addr) {
    asm volatile(
        "ldmatrix.sync.aligned.m8n8.x4.trans.shared.b16 {%0,%1,%2,%3}, [%4];"
        : "=r"(r[0]), "=r"(r[1]), "=r"(r[2]), "=r"(r[3]) : "r"(addr));
}
__device__ __forceinline__ void mma_bf16(float* d, const unsigned* a,
                                         unsigned b0, unsigned b1) {
    asm volatile(
        "mma.sync.aligned.m16n8k16.row.col.f32.bf16.bf16.f32 "
        "{%0,%1,%2,%3}, {%4,%5,%6,%7}, {%8,%9}, {%0,%1,%2,%3};"
        : "+f"(d[0]), "+f"(d[1]), "+f"(d[2]), "+f"(d[3])
        : "r"(a[0]), "r"(a[1]), "r"(a[2]), "r"(a[3]), "r"(b0), "r"(b1));
}

// fp32 pair -> bf16x2 hi + bf16x2 lo (split for precision recovery)
__device__ __forceinline__ void cvt_split2(float x0, float x1,
                                           unsigned& h, unsigned& l) {
    asm("cvt.rn.satfinite.bf16x2.f32 %0, %1, %2;" : "=r"(h) : "f"(x1), "f"(x0));
    float hf0 = __uint_as_float(h << 16);
    float hf1 = __uint_as_float(h & 0xffff0000u);
    float l0 = x0 - hf0;
    float l1 = x1 - hf1;
    asm("cvt.rn.satfinite.bf16x2.f32 %0, %1, %2;" : "=r"(l) : "f"(l1), "f"(l0));
}
__device__ __forceinline__ void split_store(float4 a, float4 b,
                                            char* dst_hi, char* dst_lo) {
    uint4 h, l;
    cvt_split2(a.x, a.y, h.x, l.x);
    cvt_split2(a.z, a.w, h.y, l.y);
    cvt_split2(b.x, b.y, h.z, l.z);
    cvt_split2(b.z, b.w, h.w, l.w);
    *(uint4*)dst_hi = h;
    *(uint4*)dst_lo = l;
}

// cp.async 16B (bypass-L1)
__device__ __forceinline__ void cp_async16(void* smem_ptr, const void* gptr) {
    unsigned saddr = (unsigned)__cvta_generic_to_shared(smem_ptr);
    asm volatile("cp.async.cg.shared.global [%0], [%1], 16;"
                 :: "r"(saddr), "l"(gptr) : "memory");
}
__device__ __forceinline__ void cp_commit() {
    asm volatile("cp.async.commit_group;" ::: "memory");
}
__device__ __forceinline__ void cp_wait0() {
    asm volatile("cp.async.wait_group 0;" ::: "memory");
}

// ---------------------------------------------------------------------------
// Tensor-core NT GEMM via mma.sync: C[m,n] = sum_k A[m,k]*W[n,k].
// CTA 128x128, K staged 64/stage, DOUBLE-BUFFERED smem (one sync/stage).
// PA: A is pre-split bf16 hi/lo (copy staging); else fp32 split on the fly.
// SC: C written as bf16 hi/lo split arrays; else fp32.
// ---------------------------------------------------------------------------
#define GK_STAGES 16
#define GK_TILE_BYTES (128 * 64 * 2)            // 16384 per tensor-half
#define GK_BUF_BYTES (4 * GK_TILE_BYTES)        // Ah, Al, Bh, Bl = 64 KB
#define GEMM_SMEM (2 * GK_BUF_BYTES + 1024)

template <bool PA, bool SC>
__device__ __forceinline__ void gemm_body(
    const float* __restrict__ A,
    const uint4* __restrict__ Ah4, const uint4* __restrict__ Al4,
    const float* __restrict__ W,
    float* __restrict__ C,
    unsigned* __restrict__ Ch, unsigned* __restrict__ Cl) {
    extern __shared__ char dyn_raw[];
    char* dynb = (char*)(((unsigned long long)(size_t)dyn_raw + 1023ull) &
                         ~1023ull);

    const int tid = threadIdx.x;
    const int wid = tid >> 5;
    const int lane = tid & 31;
    const int m0 = blockIdx.y * 128;
    const int n0 = blockIdx.x * 128;

    const unsigned smem_base = smem_u32(dynb);

    const float4* A4 = (const float4*)A;
    const float4* W4 = (const float4*)W;

    const int rb0 = tid >> 3;     // 0..31
    const int cc  = tid & 7;

    const int wm = (wid >> 2) * 64;
    const int wn = (wid & 3) * 32;
    const int arow = lane & 15;
    const unsigned axor = (unsigned)((arow & 7) << 4);
    const unsigned ahi = (unsigned)(lane >> 4);
    const int brow = (lane & 7) + ((lane >> 4) << 3);
    const unsigned bxor = (unsigned)((brow & 7) << 4);
    const unsigned bhi = (unsigned)((lane >> 3) & 1);

    float d[4][4][4];
#pragma unroll
    for (int i = 0; i < 4; i++)
#pragma unroll
        for (int j = 0; j < 4; j++)
#pragma unroll
            for (int c = 0; c < 4; c++) d[i][j][c] = 0.0f;

    float4 ra[4][2], rb_[4][2];
    uint4 pa[8];

#define GK_LDG(s)                                                          \
    do {                                                                   \
        _Pragma("unroll")                                                  \
        for (int i = 0; i < 4; i++) {                                      \
            const int r = rb0 + 32 * i;                                    \
            if (PA) {                                                      \
                const size_t gi = (size_t)(m0 + r) * 128 + (s) * 8 + cc;   \
                pa[i] = Ah4[gi];                                           \
                pa[i + 4] = Al4[gi];                                       \
            } else {                                                       \
                const size_t ga = (size_t)(m0 + r) * 256 + (s) * 16 + cc * 2;\
                ra[i][0] = A4[ga];                                         \
                ra[i][1] = A4[ga + 1];                                     \
            }                                                              \
            const size_t gb = (size_t)(n0 + r) * 256 + (s) * 16 + cc * 2;  \
            rb_[i][0] = W4[gb];                                            \
            rb_[i][1] = W4[gb + 1];                                        \
        }                                                                  \
    } while (0)

#define GK_STS(buf)                                                        \
    do {                                                                   \
        char* Ah = dynb + (buf) * GK_BUF_BYTES;                            \
        char* Al = Ah + GK_TILE_BYTES;                                     \
        char* Bh = Ah + 2 * GK_TILE_BYTES;                                 \
        char* Bl = Ah + 3 * GK_TILE_BYTES;                                 \
        _Pragma("unroll")                                                  \
        for (int i = 0; i < 4; i++) {                                      \
            const int r = rb0 + 32 * i;                                    \
            const unsigned off = (unsigned)(r * 128 + cc * 16);            \
            const unsigned sw = off ^ ((off >> 3) & 0x70);                 \
            if (PA) {                                                      \
                *(uint4*)(Ah + sw) = pa[i];                                \
                *(uint4*)(Al + sw) = pa[i + 4];                            \
            } else {                                                       \
                split_store(ra[i][0], ra[i][1], Ah + sw, Al + sw);         \
            }                                                              \
            split_store(rb_[i][0], rb_[i][1], Bh + sw, Bl + sw);           \
        }                                                                  \
    } while (0)

    GK_LDG(0);
    GK_STS(0);
    GK_LDG(1);
    __syncthreads();

    for (int s = 0; s < GK_STAGES; s++) {
        const int cur = s & 1;
        if (s + 1 < GK_STAGES) GK_STS(cur ^ 1);
        if (s + 2 < GK_STAGES) GK_LDG(s + 2);

        const unsigned bo = smem_base + (unsigned)cur * GK_BUF_BYTES;
        const unsigned sA_h = bo;
        const unsigned sA_l = bo + GK_TILE_BYTES;
        const unsigned sB_h = bo + 2 * GK_TILE_BYTES;
        const unsigned sB_l = bo + 3 * GK_TILE_BYTES;

#pragma unroll
        for (int ks = 0; ks < 4; ks++) {
            unsigned bh[2][4], bl[2][4];
#pragma unroll
            for (int j2 = 0; j2 < 2; j2++) {
                const unsigned roff =
                    (unsigned)(wn + 16 * j2 + brow) * 128 +
                    ((((unsigned)(2 * ks) + bhi) << 4) ^ bxor);
                ldmx4(bh[j2], sB_h + roff);
                ldmx4(bl[j2], sB_l + roff);
            }
#pragma unroll
            for (int i = 0; i < 4; i++) {
                const unsigned aoff =
                    (unsigned)(wm + 16 * i + arow) * 128 +
                    ((((unsigned)(2 * ks) + ahi) << 4) ^ axor);
                unsigned ah[4], al[4];
                ldmx4(ah, sA_h + aoff);
                ldmx4(al, sA_l + aoff);
#pragma unroll
                for (int j = 0; j < 4; j++) {
                    const unsigned b0h = bh[j >> 1][(j & 1) * 2];
                    const unsigned b1h = bh[j >> 1][(j & 1) * 2 + 1];
                    const unsigned b0l = bl[j >> 1][(j & 1) * 2];
                    const unsigned b1l = bl[j >> 1][(j & 1) * 2 + 1];
                    mma_bf16(d[i][j], ah, b0h, b1h);
                    mma_bf16(d[i][j], ah, b0l, b1l);
                    mma_bf16(d[i][j], al, b0h, b1h);
                }
            }
        }
        __syncthreads();
    }
#undef GK_LDG
#undef GK_STS

    // ---- epilogue ----
    const int r0 = m0 + wm + (lane >> 2);
    const int cb = n0 + wn + 2 * (lane & 3);
    if (SC) {
#pragma unroll
        for (int i = 0; i < 4; i++)
#pragma unroll
            for (int j = 0; j < 4; j++) {
                unsigned h0, l0, h1, l1;
                cvt_split2(d[i][j][0], d[i][j][1], h0, l0);
                cvt_split2(d[i][j][2], d[i][j][3], h1, l1);
                const size_t idx =
                    (size_t)(r0 + 16 * i) * DM2 + (cb >> 1) + 4 * j;
                Ch[idx] = h0;
                Cl[idx] = l0;
                Ch[idx + 8 * DM2] = h1;
                Cl[idx + 8 * DM2] = l1;
            }
    } else {
        float* Cbase = C + (size_t)r0 * DMODEL + cb;
#pragma unroll
        for (int i = 0; i < 4; i++)
#pragma unroll
            for (int j = 0; j < 4; j++) {
                *(float2*)(Cbase + (size_t)(16 * i) * DMODEL + 8 * j) =
                    make_float2(d[i][j][0], d[i][j][1]);
                *(float2*)(Cbase + (size_t)(16 * i + 8) * DMODEL + 8 * j) =
                    make_float2(d[i][j][2], d[i][j][3]);
            }
    }
}

__global__ void __launch_bounds__(256, 1)
mha_gemm_qkv(const float* __restrict__ q, const float* __restrict__ k,
             const float* __restrict__ v, const float* __restrict__ wq,
             const float* __restrict__ wk, const float* __restrict__ wv) {
    const int z = blockIdx.z;
    const float* A = (z == 0) ? q : (z == 1) ? k : v;
    const float* W = (z == 0) ? wq : (z == 1) ? wk : wv;
    unsigned* Ch = (z == 0) ? g_Qh : (z == 1) ? g_Kh : g_Vh;
    unsigned* Cl = (z == 0) ? g_Ql : (z == 1) ? g_Kl : g_Vl;
    gemm_body<false, true>(A, nullptr, nullptr, W, nullptr, Ch, Cl);
}

__global__ void __launch_bounds__(256, 1)
mha_gemm_out(const float* __restrict__ wo, float* __restrict__ out) {
    gemm_body<true, false>(nullptr, (const uint4*)g_Xh, (const uint4*)g_Xl,
                           wo, out, nullptr, nullptr);
}

// ---------------------------------------------------------------------------
// Tensor-core flash attention, pre-split inputs + cp.async double buffering.
// CTA = 128 q-rows x one (batch, head); 256 threads = 8 warps x 16 rows.
// K/V tiles (64 x 64 bf16 hi/lo) copied (no CVT) via cp.async into SW128
// smem, double buffered; Q staged once via buffer 1 and held in registers.
// ---------------------------------------------------------------------------
#define ATT_BM 128
#define ATT_BN 64
#define ATT_TILE_B (ATT_BN * 128)            // 8 KB per tensor-half tile
#define ATT_BUF_B (4 * ATT_TILE_B)           // Kh,Kl,Vh,Vl = 32 KB
#define ATT_SMEM (2 * ATT_BUF_B + 1024)

__global__ void __launch_bounds__(256, 1)
mha_flash_attn_tc(const int* __restrict__ mask) {
    extern __shared__ char att_raw[];
    char* base = (char*)(((unsigned long long)(size_t)att_raw + 1023ull) &
                         ~1023ull);
    const unsigned sbase = smem_u32(base);

    const int tid = threadIdx.x;
    const int wid = tid >> 5;
    const int lane = tid & 31;
    const int q0 = blockIdx.x * ATT_BM;
    const int bh = blockIdx.y;
    const int b = bh >> 4;
    const int h = bh & 15;

    // ---- prologue: Q -> buf1 (copy), K/V tile 0 -> buf0, one group ----
#pragma unroll
    for (int i = 0; i < 8; i++) {               // K/V tile 0
        const int idx = tid + 256 * i;          // 0..2047
        const int t = i >> 1;                   // 0..3: Kh,Kl,Vh,Vl
        const int idx2 = (idx & 511);
        const int r = idx2 >> 3, cc = idx2 & 7;
        const unsigned* src =
            (t == 0) ? g_Kh : (t == 1) ? g_Kl : (t == 2) ? g_Vh : g_Vl;
        const size_t gi = (size_t)(b * SEQ + r) * DM2 + h * 32 + cc * 4;
        char* dst = base + t * ATT_TILE_B + r * 128 + (((cc ^ (r & 7))) << 4);
        cp_async16(dst, src + gi);
    }
#pragma unroll
    for (int i = 0; i < 8; i++) {               // Q -> buf1
        const int idx = tid + 256 * i;          // 0..2047
        const int half = i >> 2;                // 0: hi, 1: lo
        const int idx2 = idx & 1023;
        const int r = idx2 >> 3, cc = idx2 & 7;
        const unsigned* src = half ? g_Ql : g_Qh;
        const size_t gi = (size_t)(b * SEQ + q0 + r) * DM2 + h * 32 + cc * 4;
        char* dst = base + ATT_BUF_B + half * (2 * ATT_TILE_B) +
                    r * 128 + (((cc ^ (r & 7))) << 4);
        cp_async16(dst, src + gi);
    }
    cp_commit();
    cp_wait0();
    __syncthreads();

    // ---- Q fragments (registers, whole kernel) ----
    unsigned qh[4][4], ql[4][4];
    {
        const int arow = lane & 15;
        const unsigned ahi = (unsigned)(lane >> 4);
        const int row = 16 * wid + arow;
#pragma unroll
        for (int kk = 0; kk < 4; kk++) {
            const unsigned ch = 2 * (unsigned)kk + ahi;
            const unsigned off =
                (unsigned)(row * 128) + ((ch ^ (unsigned)(row & 7)) << 4);
            ldmx4(qh[kk], sbase + ATT_BUF_B + off);
            ldmx4(ql[kk], sbase + ATT_BUF_B + 2 * ATT_TILE_B + off);
        }
    }
    __syncthreads();   // all warps done reading Q from buf1

    float o[8][4];
#pragma unroll
    for (int j = 0; j < 8; j++)
#pragma unroll
        for (int e = 0; e < 4; e++) o[j][e] = 0.0f;
    float m0 = -1e30f, m1 = -1e30f, l0 = 0.0f, l1 = 0.0f;

    const int grow = q0 + 16 * wid + (lane >> 2);
    const int* mrow0 = mask + ((size_t)b * SEQ + grow) * SEQ;
    const int* mrow1 = mrow0 + 8 * SEQ;

    const int brow = (lane & 7) + ((lane >> 4) << 3);
    const unsigned bxor = (unsigned)((brow & 7) << 4);
    const unsigned bhi = (unsigned)((lane >> 3) & 1);
    const int vtt = lane >> 3;
    const int vrow_lo = ((vtt & 1) << 3) + (lane & 7);
    const unsigned vch_add = (unsigned)(vtt >> 1);

    for (int n = 0; n < SEQ / ATT_BN; n++) {
        const int j0 = n * ATT_BN;
        const int cur = n & 1;
        if (n > 0) {
            cp_wait0();        // tile n arrived
            __syncthreads();   // compute(n-1) finished -> buf[cur^1] free
        }
        if (n + 1 < SEQ / ATT_BN) {   // prefetch tile n+1 into other buffer
            char* bufn = base + (cur ^ 1) * ATT_BUF_B;
            const int jn = j0 + ATT_BN;
#pragma unroll
            for (int i = 0; i < 8; i++) {
                const int idx = tid + 256 * i;
                const int t = i >> 1;
                const int idx2 = (idx & 511);
                const int r = idx2 >> 3, cc = idx2 & 7;
                const unsigned* src =
                    (t == 0) ? g_Kh : (t == 1) ? g_Kl : (t == 2) ? g_Vh : g_Vl;
                const size_t gi =
                    (size_t)(b * SEQ + jn + r) * DM2 + h * 32 + cc * 4;
                char* dst =
                    bufn + t * ATT_TILE_B + r * 128 + (((cc ^ (r & 7))) << 4);
                cp_async16(dst, src + gi);
            }
            cp_commit();
        }

        const unsigned bo = sbase + (unsigned)cur * ATT_BUF_B;
        const unsigned sKh = bo;
        const unsigned sKl = bo + ATT_TILE_B;
        const unsigned sVh = bo + 2 * ATT_TILE_B;
        const unsigned sVl = bo + 3 * ATT_TILE_B;

        // ---- S = Q.K^T (3-way split) ----
        float c[8][4];
#pragma unroll
        for (int j = 0; j < 8; j++)
#pragma unroll
            for (int e = 0; e < 4; e++) c[j][e] = 0.0f;

#pragma unroll
        for (int ks = 0; ks < 4; ks++) {
#pragma unroll
            for (int j2 = 0; j2 < 4; j2++) {
                const int kr = 16 * j2 + brow;
                const unsigned off = (unsigned)(kr * 128) +
                    ((((unsigned)(2 * ks) + bhi) << 4) ^ bxor);
                unsigned kbh[4], kbl[4];
                ldmx4(kbh, sKh + off);
                ldmx4(kbl, sKl + off);
#pragma unroll
                for (int jj = 0; jj < 2; jj++) {
                    const int j = 2 * j2 + jj;
                    mma_bf16(c[j], qh[ks], kbh[2 * jj], kbh[2 * jj + 1]);
                    mma_bf16(c[j], qh[ks], kbl[2 * jj], kbl[2 * jj + 1]);
                    mma_bf16(c[j], ql[ks], kbh[2 * jj], kbh[2 * jj + 1]);
                }
            }
        }

        // ---- scale + mask ----
        const int mcol = j0 + 2 * (lane & 3);
#pragma unroll
        for (int j = 0; j < 8; j++) {
            const int2 mv0 = *(const int2*)(mrow0 + mcol + 8 * j);
            const int2 mv1 = *(const int2*)(mrow1 + mcol + 8 * j);
            c[j][0] = mv0.x ? c[j][0] * 0.125f : -1e9f;
            c[j][1] = mv0.y ? c[j][1] * 0.125f : -1e9f;
            c[j][2] = mv1.x ? c[j][2] * 0.125f : -1e9f;
            c[j][3] = mv1.y ? c[j][3] * 0.125f : -1e9f;
        }

        // ---- row max (quad shuffle reduce) ----
        float t0 = -1e30f, t1 = -1e30f;
#pragma unroll
        for (int j = 0; j < 8; j++) {
            t0 = fmaxf(t0, fmaxf(c[j][0], c[j][1]));
            t1 = fmaxf(t1, fmaxf(c[j][2], c[j][3]));
        }
        t0 = fmaxf(t0, __shfl_xor_sync(0xffffffffu, t0, 1));
        t0 = fmaxf(t0, __shfl_xor_sync(0xffffffffu, t0, 2));
        t1 = fmaxf(t1, __shfl_xor_sync(0xffffffffu, t1, 1));
        t1 = fmaxf(t1, __shfl_xor_sync(0xffffffffu, t1, 2));

        const float mn0 = fmaxf(m0, t0);
        const float mn1 = fmaxf(m1, t1);
        const float al0 = __expf(m0 - mn0);
        const float al1 = __expf(m1 - mn1);
        m0 = mn0; m1 = mn1;
        l0 *= al0; l1 *= al1;
#pragma unroll
        for (int j = 0; j < 8; j++) {
            o[j][0] *= al0; o[j][1] *= al0;
            o[j][2] *= al1; o[j][3] *= al1;
        }

        // ---- exponentiate, accumulate row sums ----
#pragma unroll
        for (int j = 0; j < 8; j++) {
            c[j][0] = __expf(c[j][0] - m0);
            c[j][1] = __expf(c[j][1] - m0);
            c[j][2] = __expf(c[j][2] - m1);
            c[j][3] = __expf(c[j][3] - m1);
            l0 += c[j][0] + c[j][1];
            l1 += c[j][2] + c[j][3];
        }

        // ---- O += P.V (register repack, 3-way split) ----
#pragma unroll
        for (int kk = 0; kk < 4; kk++) {
            unsigned pah[4], pal[4];
            cvt_split2(c[2 * kk][0],     c[2 * kk][1],     pah[0], pal[0]);
            cvt_split2(c[2 * kk][2],     c[2 * kk][3],     pah[1], pal[1]);
            cvt_split2(c[2 * kk + 1][0], c[2 * kk + 1][1], pah[2], pal[2]);
            cvt_split2(c[2 * kk + 1][2], c[2 * kk + 1][3], pah[3], pal[3]);
#pragma unroll
            for (int j2 = 0; j2 < 4; j2++) {
                const int vr = 16 * kk + vrow_lo;
                const unsigned ch = 2 * (unsigned)j2 + vch_add;
                const unsigned off = (unsigned)(vr * 128) +
                    ((ch ^ (unsigned)(vr & 7)) << 4);
                unsigned vbh[4], vbl[4];
                ldmx4t(vbh, sVh + off);
                ldmx4t(vbl, sVl + off);
#pragma unroll
                for (int jj = 0; jj < 2; jj++) {
                    const int j = 2 * j2 + jj;
                    mma_bf16(o[j], pah, vbh[2 * jj], vbh[2 * jj + 1]);
                    mma_bf16(o[j], pah, vbl[2 * jj], vbl[2 * jj + 1]);
                    mma_bf16(o[j], pal, vbh[2 * jj], vbh[2 * jj + 1]);
                }
            }
        }
    }

    // ---- finalize: full row sums, normalize, write g_Xh/g_Xl ----
    l0 += __shfl_xor_sync(0xffffffffu, l0, 1);
    l0 += __shfl_xor_sync(0xffffffffu, l0, 2);
    l1 += __shfl_xor_sync(0xffffffffu, l1, 1);
    l1 += __shfl_xor_sync(0xffffffffu, l1, 2);
    const float inv0 = 1.0f / l0;
    const float inv1 = 1.0f / l1;

    const size_t xrow = (size_t)(b * SEQ + grow) * DM2 + h * 32 + (lane & 3);
#pragma unroll
    for (int j = 0; j < 8; j++) {
        unsigned h0, lo0, h1, lo1;
        cvt_split2(o[j][0] * inv0, o[j][1] * inv0, h0, lo0);
        cvt_split2(o[j][2] * inv1, o[j][3] * inv1, h1, lo1);
        g_Xh[xrow + 4 * j] = h0;
        g_Xl[xrow + 4 * j] = lo0;
        g_Xh[xrow + 8 * DM2 + 4 * j] = h1;
        g_Xl[xrow + 8 * DM2 + 4 * j] = lo1;
    }
}

// ---------------------------------------------------------------------------
// Launch
// Inputs (metadata order): q, k, v, w_q, w_k, w_v, w_o, mask
// ---------------------------------------------------------------------------
extern "C" void kernel_launch(void* const* d_in, const int* in_sizes, int n_in,
                              void* d_out, int out_size) {
    const float* q  = (const float*)d_in[0];
    const float* k  = (const float*)d_in[1];
    const float* v  = (const float*)d_in[2];
    const float* wq = (const float*)d_in[3];
    const float* wk = (const float*)d_in[4];
    const float* wv = (const float*)d_in[5];
    const float* wo = (const float*)d_in[6];
    const int* mask = (const int*)d_in[7];
    float* out = (float*)d_out;

    cudaFuncSetAttribute(mha_gemm_qkv,
                         cudaFuncAttributeMaxDynamicSharedMemorySize, GEMM_SMEM);
    cudaFuncSetAttribute(mha_gemm_out,
                         cudaFuncAttributeMaxDynamicSharedMemorySize, GEMM_SMEM);
    cudaFuncSetAttribute(mha_flash_attn_tc,
                         cudaFuncAttributeMaxDynamicSharedMemorySize, ATT_SMEM);

    // Q/K/V projections: grid (N/128, M/128, 3), write split bf16
    dim3 gqkv(DMODEL / 128, MROWS / 128, 3);
    mha_gemm_qkv<<<gqkv, 256, GEMM_SMEM>>>(q, k, v, wq, wk, wv);

    // attention: grid (S/128, B*H), tensor-core flash attention
    dim3 gatt(SEQ / ATT_BM, BATCH * NHEAD);
    mha_flash_attn_tc<<<gatt, 256, ATT_SMEM>>>(mask);

    // output projection (A pre-split)
    dim3 gout(DMODEL / 128, MROWS / 128, 1);
    mha_gemm_out<<<gout, 256, GEMM_SMEM>>>(wo, out);
}